// round 3
// baseline (speedup 1.0000x reference)
#include <cuda_runtime.h>

// ---------------- problem constants (fixed by setup_inputs) ----------------
#define G        64      // gt boxes per batch
#define A        5       // anchors per location
#define S        25      // score map size
#define NANCH    3125    // S*S*A
#define BMAX     128     // batch
#define POS_NUM  16
#define TOTAL_NUM 64
#define THR_HIGH 0.6f
#define THR_LOW  0.3f

// ---------------- scratch (device globals; no allocation allowed) ----------
__device__ unsigned    g_gtmax[BMAX * G];   // per-(b,g) max IoU as float bits
__device__ signed char g_cls  [BMAX * NANCH];
__device__ int         g_poscnt;

// ---------------- K0: zero scratch -----------------------------------------
__global__ void k_init() {
    int i = blockIdx.x * blockDim.x + threadIdx.x;
    if (i < BMAX * G) g_gtmax[i] = 0u;
    if (i == 0) g_poscnt = 0;
}

// IEEE round-to-nearest IoU. Explicit _rn intrinsics: non-contractible, so the
// two passes below produce BITWISE identical values (required for the == keep).
__device__ __forceinline__ float iou_rn(float ax1, float ay1, float ax2, float ay2,
                                        float area_a,
                                        float gx1, float gy1, float gx2, float gy2,
                                        float area_g) {
    float ix = __fadd_rn(__fsub_rn(fminf(ax2, gx2), fmaxf(ax1, gx1)), 1.0f);
    float iy = __fadd_rn(__fsub_rn(fminf(ay2, gy2), fmaxf(ay1, gy1)), 1.0f);
    float inter = __fmul_rn(fmaxf(ix, 0.0f), fmaxf(iy, 0.0f));
    float denom = __fsub_rn(__fadd_rn(area_a, area_g), inter);
    return __fdiv_rn(inter, denom);
}

// ---------------- K1: per-gt max IoU over all anchors ----------------------
// grid ((N+127)/128, B), 128 threads. Warp-redux per g, then smem, then global.
__global__ void k_gtmax(const float4* __restrict__ anchors,
                        const float4* __restrict__ gt) {
    __shared__ float4   s_gtv[G];
    __shared__ float    s_gar[G];
    __shared__ unsigned s_gtm[G];

    const int bA   = blockIdx.y;
    const int base = blockIdx.x * 128;
    const int t    = threadIdx.x;

    if (t < G) {
        float4 q = gt[bA * G + t];
        s_gtv[t] = q;
        float gw = __fadd_rn(__fsub_rn(q.z, q.x), 1.0f);
        float gh = __fadd_rn(__fsub_rn(q.w, q.y), 1.0f);
        s_gar[t] = __fmul_rn(gw, gh);
        s_gtm[t] = 0u;
    }
    __syncthreads();

    const int  n     = base + t;
    const bool valid = (n < NANCH);
    float4 a4 = anchors[valid ? n : 0];
    float aw = __fadd_rn(__fsub_rn(a4.z, a4.x), 1.0f);
    float ah = __fadd_rn(__fsub_rn(a4.w, a4.y), 1.0f);
    float area_a = __fmul_rn(aw, ah);

#pragma unroll 4
    for (int g = 0; g < G; g++) {
        float4 q = s_gtv[g];
        float v = iou_rn(a4.x, a4.y, a4.z, a4.w, area_a,
                         q.x, q.y, q.z, q.w, s_gar[g]);
        unsigned u = valid ? __float_as_uint(v) : 0u;   // v >= 0 -> bits monotonic
        unsigned m = __reduce_max_sync(0xffffffffu, u);
        if ((t & 31) == 0 && m) atomicMax(&s_gtm[g], m);
    }
    __syncthreads();
    if (t < G && s_gtm[t]) atomicMax(&g_gtmax[bA * G + t], s_gtm[t]);
}

// ---------------- K2: recompute IoUs -> max/arg/keep, cls, bt, maxov -------
__global__ void k_main(const float4* __restrict__ anchors,
                       const float4* __restrict__ gt,
                       float* __restrict__ out, int Bn) {
    __shared__ float4   s_gtv[G];
    __shared__ float    s_gar[G];
    __shared__ unsigned s_gtm[G];

    const int bA   = blockIdx.y;
    const int base = blockIdx.x * 128;
    const int t    = threadIdx.x;

    if (t < G) {
        float4 q = gt[bA * G + t];
        s_gtv[t] = q;
        float gw = __fadd_rn(__fsub_rn(q.z, q.x), 1.0f);
        float gh = __fadd_rn(__fsub_rn(q.w, q.y), 1.0f);
        s_gar[t] = __fmul_rn(gw, gh);
        s_gtm[t] = g_gtmax[bA * G + t];
    }
    __syncthreads();

    const int n = base + t;
    if (n >= NANCH) return;

    float4 a4 = anchors[n];
    float aw = __fadd_rn(__fsub_rn(a4.z, a4.x), 1.0f);
    float ah = __fadd_rn(__fsub_rn(a4.w, a4.y), 1.0f);
    float area_a = __fmul_rn(aw, ah);

    float maxv = -1.0f;
    int   arg  = 0;
    bool  keep = false;
#pragma unroll 4
    for (int g = 0; g < G; g++) {
        float4 q = s_gtv[g];
        float v = iou_rn(a4.x, a4.y, a4.z, a4.w, area_a,
                         q.x, q.y, q.z, q.w, s_gar[g]);
        if (v > maxv) { maxv = v; arg = g; }          // strict >: first argmax
        unsigned gm = s_gtm[g];
        keep |= (gm != 0u) && (__float_as_uint(v) == gm);
    }

    const long idx = (long)bA * NANCH + n;
    int cls = -1;
    if (maxv >= THR_HIGH) cls = 1;
    if (maxv <= THR_LOW)  cls = 0;
    if (keep)             cls = 1;
    g_cls[idx] = (signed char)cls;
    if (bA == Bn - 1 && cls == 1) atomicAdd(&g_poscnt, 1);

    // max_ov output (region 6)
    out[(long)Bn * NANCH * 6 + idx] = maxv;

    // bt deltas (region 1..4), transposed to (b, 4, A, S, S)
    float4 q = s_gtv[arg];
    float acx = a4.x + 0.5f * aw, acy = a4.y + 0.5f * ah;
    float gw = q.z - q.x + 1.0f,  gh = q.w - q.y + 1.0f;
    float gcx = q.x + 0.5f * gw,  gcy = q.y + 0.5f * gh;
    float dx = __fdividef(gcx - acx, aw);
    float dy = __fdividef(gcy - acy, ah);
    float dw = __logf(__fdividef(gw, aw));
    float dh = __logf(__fdividef(gh, ah));

    const int a = n % A, yx = n / A;
    long o = (long)Bn * NANCH + ((long)(bA * 4) * A + a) * (S * S) + yx;
    out[o]             = dx;
    out[o + NANCH]     = dy;      // +1 delta-channel = +A*S*S = NANCH
    out[o + 2 * NANCH] = dw;
    out[o + 3 * NANCH] = dh;
}

// ---------------- K3: per-batch pos/neg cumsum truncation, cls/bw writes ---
__global__ void k_scan(float* __restrict__ out, int Bn) {
    __shared__ int wsum[4];
    const int bA = blockIdx.x;
    const int t  = threadIdx.x;                      // 128 threads
    const int CH = (NANCH + 127) / 128;              // 25
    const int start = t * CH;
    const int end   = min(start + CH, NANCH);

    int pc = 0, nc = 0;
    for (int n = start; n < end; n++) {
        int c = g_cls[(long)bA * NANCH + n];
        pc += (c == 1);
        nc += (c == 0);
    }
    int v = (pc << 16) | nc;                         // counts fit 16 bits each
    const int lane = t & 31, wid = t >> 5;
    int inc = v;
#pragma unroll
    for (int off = 1; off < 32; off <<= 1) {
        int u = __shfl_up_sync(0xffffffffu, inc, off);
        if (lane >= off) inc += u;
    }
    if (lane == 31) wsum[wid] = inc;
    __syncthreads();
    int exc = inc - v;
    for (int w = 0; w < wid; w++) exc += wsum[w];
    int prun = exc >> 16;
    int nrun = exc & 0xffff;

    const int pn = min(g_poscnt, POS_NUM);
    const float invp = 1.0f / (float)pn;             // pn==0 -> inf, matches ref
    const long bwOff = (long)Bn * NANCH * 5;         // cls(1) + bt(4)

    for (int n = start; n < end; n++) {
        int c = g_cls[(long)bA * NANCH + n];
        if (c == 1)      { prun++; if (prun > POS_NUM)   c = -1; }
        else if (c == 0) { nrun++; if (nrun > TOTAL_NUM) c = -1; }
        float bw = (c == 1) ? invp : 0.0f;
        int a = n % A, yx = n / A;
        long ci = ((long)bA * A + a) * (S * S) + yx;
        out[ci]         = (float)c;
        out[bwOff + ci] = bw;
    }
}

// ---------------- launch ----------------------------------------------------
extern "C" void kernel_launch(void* const* d_in, const int* in_sizes, int n_in,
                              void* d_out, int out_size) {
    (void)n_in; (void)out_size;
    const float4* gt      = (const float4*)d_in[0];   // (B, G, 4)
    const float4* anchors = (const float4*)d_in[1];   // (N, 4)
    const int Bn = in_sizes[0] / (G * 4);             // 128
    float* out = (float*)d_out;

    k_init<<<(BMAX * G + 255) / 256, 256>>>();

    dim3 g1((NANCH + 127) / 128, Bn);
    k_gtmax<<<g1, 128>>>(anchors, gt);
    k_main <<<g1, 128>>>(anchors, gt, out, Bn);
    k_scan <<<Bn, 128>>>(out, Bn);
}